// round 1
// baseline (speedup 1.0000x reference)
#include <cuda_runtime.h>

// SphereDownGeo: y[b=0, c, k] = sum_d M_vals[k,d] * x[0, c, M_cols[k,d]]
// M_cols[k,d] = clip(4k + off, 0, N_IN-1) with off in [-6, 9]  -> strong locality.
//
// Strategy: block handles KB=256 consecutive k. All needed x columns lie in a
// window [4*k0-8, 4*k0+1037] (<=1044 floats) per channel. Stage 8 channels of
// that window in shared memory with coalesced float4 loads (x read from HBM
// exactly once), then each thread gathers its 16 (col, val) pairs from smem
// for all 8 channels.

#define N_IN   3145728
#define K_OUT  786432
#define DEG    16
#define CCH    8
#define KB     256
#define WINV   261            // float4 vectors per channel window (261*4 = 1044 floats)
#define WIN    (WINV * 4)     // 1044
#define STRIDE 1048           // smem row stride (floats), 16B aligned

__global__ __launch_bounds__(KB) void sphere_down_kernel(
    const float* __restrict__ x,
    const int*   __restrict__ M_cols,
    const float* __restrict__ M_vals,
    const int*   __restrict__ cell_ids,
    float*       __restrict__ out,
    int write_ids)
{
    __shared__ float sx[CCH * STRIDE];

    const int k0   = blockIdx.x * KB;
    const int w_lo = (max(0, 4 * k0 - 6)) & ~3;   // 16B-aligned window start

    // ---- Stage window: 8 channels x 1044 floats, coalesced float4 loads ----
    for (int i = threadIdx.x; i < CCH * WINV; i += KB) {
        const int c = i / WINV;
        const int j = i - c * WINV;
        const int g = w_lo + 4 * j;
        float4 v;
        if (g + 3 < N_IN) {
            v = *reinterpret_cast<const float4*>(x + (size_t)c * N_IN + g);
        } else {
            v.x = (g + 0 < N_IN) ? x[(size_t)c * N_IN + g + 0] : 0.0f;
            v.y = (g + 1 < N_IN) ? x[(size_t)c * N_IN + g + 1] : 0.0f;
            v.z = (g + 2 < N_IN) ? x[(size_t)c * N_IN + g + 2] : 0.0f;
            v.w = (g + 3 < N_IN) ? x[(size_t)c * N_IN + g + 3] : 0.0f;
        }
        float* s = sx + c * STRIDE + 4 * j;
        s[0] = v.x; s[1] = v.y; s[2] = v.z; s[3] = v.w;
    }
    __syncthreads();

    // ---- Per-thread k: load 16 (col, val) pairs with vector loads ----
    const int k = k0 + threadIdx.x;   // K_OUT = 3072 * 256 exactly, no guard needed

    const int4*   cp = reinterpret_cast<const int4*>(M_cols + (size_t)k * DEG);
    const float4* vp = reinterpret_cast<const float4*>(M_vals + (size_t)k * DEG);

    int   cols[DEG];
    float vals[DEG];
    #pragma unroll
    for (int q = 0; q < 4; q++) {
        int4   ci = cp[q];
        float4 vi = vp[q];
        cols[4*q + 0] = ci.x; cols[4*q + 1] = ci.y; cols[4*q + 2] = ci.z; cols[4*q + 3] = ci.w;
        vals[4*q + 0] = vi.x; vals[4*q + 1] = vi.y; vals[4*q + 2] = vi.z; vals[4*q + 3] = vi.w;
    }

    float acc[CCH];
    #pragma unroll
    for (int c = 0; c < CCH; c++) acc[c] = 0.0f;

    #pragma unroll
    for (int d = 0; d < DEG; d++) {
        const int   local = cols[d] - w_lo;   // guaranteed in [0, WIN)
        const float w     = vals[d];
        #pragma unroll
        for (int c = 0; c < CCH; c++) {
            acc[c] = fmaf(w, sx[c * STRIDE + local], acc[c]);
        }
    }

    // ---- Write y: out[c * K_OUT + k], coalesced per channel ----
    #pragma unroll
    for (int c = 0; c < CCH; c++) {
        out[(size_t)c * K_OUT + k] = acc[c];
    }

    // ---- Tail: cell_ids passthrough (as numeric value in output dtype) ----
    if (write_ids) {
        out[(size_t)CCH * K_OUT + k] = (float)cell_ids[k];
    }
}

extern "C" void kernel_launch(void* const* d_in, const int* in_sizes, int n_in,
                              void* d_out, int out_size)
{
    const float* x        = (const float*)d_in[0];
    const int*   M_cols   = (const int*)d_in[1];
    const float* M_vals   = (const float*)d_in[2];
    const int*   cell_ids = (const int*)d_in[3];
    float*       out      = (float*)d_out;

    const int y_len     = CCH * K_OUT;                  // 6,291,456
    const int write_ids = (out_size >= y_len + K_OUT) ? 1 : 0;

    dim3 grid(K_OUT / KB);   // 3072 blocks
    dim3 block(KB);
    sphere_down_kernel<<<grid, block>>>(x, M_cols, M_vals, cell_ids, out, write_ids);
}

// round 3
// speedup vs baseline: 1.2557x; 1.2557x over previous
#include <cuda_runtime.h>

// SphereDownGeo: y[c,k] = sum_d M_vals[k,d] * x[c, M_cols[k,d]],  C=8, DEG=16
// M_cols[k,d] = clip(4k + off, 0, N_IN-1), off in [-6, 9] -> windowed locality.
//
// R2/R3: channel-major smem window + XOR swizzle.
//   smem s4[i] (float4) holds channels {4h..4h+3} of column `local`, i = local*2 + h,
//   stored at swizzled index i ^ ((i>>3) & 7).  Gather = 2 x LDS.128 per (k,d)
//   covering all 8 channels (was 8 x LDS.32, 4-way conflicted).

#define N_IN   3145728
#define K_OUT  786432
#define DEG    16
#define CCH    8
#define KB     256
#define WINV   261            // float4-column-vectors per window (261*4 = 1044 cols)
#define WIN    (WINV * 4)     // 1044 columns
#define S4N    2088           // WIN*2 float4 slots (multiple of 8 for swizzle)

__device__ __forceinline__ int swz(int i) { return i ^ ((i >> 3) & 7); }

__global__ __launch_bounds__(KB) void sphere_down_kernel(
    const float* __restrict__ x,
    const int*   __restrict__ M_cols,
    const float* __restrict__ M_vals,
    const int*   __restrict__ cell_ids,
    float*       __restrict__ out,
    int write_ids)
{
    __shared__ float4 s4[S4N];

    const int k0   = blockIdx.x * KB;
    const int w_lo = (max(0, 4 * k0 - 6)) & ~3;   // 16B-aligned window start

    // ---- Stage window, transposed to channel-major ----
    for (int item = threadIdx.x; item < 2 * WINV; item += KB) {
        const int half = (item >= WINV) ? 1 : 0;
        const int jvec = item - half * WINV;
        const int g    = w_lo + 4 * jvec;

        float4 r[4];   // r[cc] = x[4*half+cc][g..g+3]
        #pragma unroll
        for (int cc = 0; cc < 4; cc++) {
            const size_t base = (size_t)(4 * half + cc) * N_IN + g;
            if (g + 3 < N_IN) {
                r[cc] = *reinterpret_cast<const float4*>(x + base);
            } else {
                r[cc].x = (g + 0 < N_IN) ? x[base + 0] : 0.0f;
                r[cc].y = (g + 1 < N_IN) ? x[base + 1] : 0.0f;
                r[cc].z = (g + 2 < N_IN) ? x[base + 2] : 0.0f;
                r[cc].w = (g + 3 < N_IN) ? x[base + 3] : 0.0f;
            }
        }
        // transpose 4x4: t[j] = (r[0][j], r[1][j], r[2][j], r[3][j])
        float4 t0 = make_float4(r[0].x, r[1].x, r[2].x, r[3].x);
        float4 t1 = make_float4(r[0].y, r[1].y, r[2].y, r[3].y);
        float4 t2 = make_float4(r[0].z, r[1].z, r[2].z, r[3].z);
        float4 t3 = make_float4(r[0].w, r[1].w, r[2].w, r[3].w);

        const int local = 4 * jvec;
        s4[swz((local + 0) * 2 + half)] = t0;
        s4[swz((local + 1) * 2 + half)] = t1;
        s4[swz((local + 2) * 2 + half)] = t2;
        s4[swz((local + 3) * 2 + half)] = t3;
    }
    __syncthreads();

    // ---- Per-thread k: gather 16 columns x 8 channels via 2 LDS.128 each ----
    const int k = k0 + threadIdx.x;   // K_OUT = 3072*256 exactly

    const int4*   cp = reinterpret_cast<const int4*>(M_cols + (size_t)k * DEG);
    const float4* vp = reinterpret_cast<const float4*>(M_vals + (size_t)k * DEG);

    int   cols[DEG];
    float vals[DEG];
    #pragma unroll
    for (int q = 0; q < 4; q++) {
        int4   ci = cp[q];
        float4 vi = vp[q];
        cols[4*q+0] = ci.x; cols[4*q+1] = ci.y; cols[4*q+2] = ci.z; cols[4*q+3] = ci.w;
        vals[4*q+0] = vi.x; vals[4*q+1] = vi.y; vals[4*q+2] = vi.z; vals[4*q+3] = vi.w;
    }

    float4 a0 = make_float4(0.f, 0.f, 0.f, 0.f);   // channels 0-3
    float4 a1 = make_float4(0.f, 0.f, 0.f, 0.f);   // channels 4-7

    #pragma unroll
    for (int d = 0; d < DEG; d++) {
        const int   local = cols[d] - w_lo;        // in [0, WIN)
        const float w     = vals[d];
        const int   i0    = local * 2;
        const int   sx    = (i0 >> 3) & 7;         // same swizzle for i0 and i0+1
        const float4 v0   = s4[i0 ^ sx];
        const float4 v1   = s4[(i0 + 1) ^ sx];
        a0.x = fmaf(w, v0.x, a0.x); a0.y = fmaf(w, v0.y, a0.y);
        a0.z = fmaf(w, v0.z, a0.z); a0.w = fmaf(w, v0.w, a0.w);
        a1.x = fmaf(w, v1.x, a1.x); a1.y = fmaf(w, v1.y, a1.y);
        a1.z = fmaf(w, v1.z, a1.z); a1.w = fmaf(w, v1.w, a1.w);
    }

    // ---- Write y: out[c * K_OUT + k], coalesced per channel ----
    out[(size_t)0 * K_OUT + k] = a0.x;
    out[(size_t)1 * K_OUT + k] = a0.y;
    out[(size_t)2 * K_OUT + k] = a0.z;
    out[(size_t)3 * K_OUT + k] = a0.w;
    out[(size_t)4 * K_OUT + k] = a1.x;
    out[(size_t)5 * K_OUT + k] = a1.y;
    out[(size_t)6 * K_OUT + k] = a1.z;
    out[(size_t)7 * K_OUT + k] = a1.w;

    if (write_ids) {
        out[(size_t)CCH * K_OUT + k] = (float)cell_ids[k];
    }
}

extern "C" void kernel_launch(void* const* d_in, const int* in_sizes, int n_in,
                              void* d_out, int out_size)
{
    const float* x        = (const float*)d_in[0];
    const int*   M_cols   = (const int*)d_in[1];
    const float* M_vals   = (const float*)d_in[2];
    const int*   cell_ids = (const int*)d_in[3];
    float*       out      = (float*)d_out;

    const int y_len     = CCH * K_OUT;
    const int write_ids = (out_size >= y_len + K_OUT) ? 1 : 0;

    dim3 grid(K_OUT / KB);   // 3072 blocks
    dim3 block(KB);
    sphere_down_kernel<<<grid, block>>>(x, M_cols, M_vals, cell_ids, out, write_ids);
}